// round 14
// baseline (speedup 1.0000x reference)
#include <cuda_runtime.h>

#define LEAK 0.2f

// Scratch (allocation-free rule: __device__ globals)
__device__ float g_c1[32u*32u*112u*112u];   // 51.4 MB
__device__ float g_c2[32u*64u*56u*56u];     // 25.7 MB
__device__ float g_c3[32u*128u*56u*56u];    // 51.4 MB
__device__ float g_flat[32u*32u*12800u];    // 52.4 MB
__device__ float g_part[2u*1024u*256u];     // FC split-K partials (2 MB)
__device__ int4   g_tabI[32*32*100];        // bilinear gather indices
__device__ float4 g_tabW[32*32*100];        // bilinear weights

typedef unsigned long long ull;

// ---- packed f32x2 helpers (sm_103a; ptxas never emits FFMA2 from C++) ----
__device__ __forceinline__ ull pack2(float x, float y) {
    ull r; asm("mov.b64 %0,{%1,%2};" : "=l"(r) : "f"(x), "f"(y)); return r;
}
__device__ __forceinline__ void unpack2(ull v, float& x, float& y) {
    asm("mov.b64 {%0,%1},%2;" : "=f"(x), "=f"(y) : "l"(v));
}
__device__ __forceinline__ void ffma2(ull& d, ull a, ull b) {
    asm("fma.rn.f32x2 %0,%1,%2,%0;" : "+l"(d) : "l"(a), "l"(b));
}

// no-op: shifts ncu's captured-launch index onto conv3
__global__ void warm_kernel() {}

// ---------------------------------------------------------------------------
// conv1: x(32,3,224,224) -> g_c1(32,32,112,112), k5 s2 p2, leaky
// block (16,16): 16x16 spatial, 4 co per thread (2 f32x2 accs). grid (7,7,256)
// ---------------------------------------------------------------------------
__global__ void conv1_kernel(const float* __restrict__ x,
                             const float* __restrict__ w,
                             const float* __restrict__ b) {
    __shared__ float sIn[3][35][36];
    __shared__ __align__(16) float sW[75][4];   // [ci*25+k][co]
    const int tid = threadIdx.y * 16 + threadIdx.x;
    const int n   = blockIdx.z >> 3;
    const int cob = blockIdx.z & 7;
    const int oy0 = blockIdx.y * 16, ox0 = blockIdx.x * 16;
    const int ih0 = oy0 * 2 - 2, iw0 = ox0 * 2 - 2;

    for (int idx = tid; idx < 3 * 35 * 35; idx += 256) {
        int ci = idx / 1225; int rem = idx - ci * 1225;
        int iy = rem / 35, ix = rem - iy * 35;
        int gy = ih0 + iy, gx = iw0 + ix;
        float v = 0.f;
        if (gy >= 0 && gy < 224 && gx >= 0 && gx < 224)
            v = x[((n * 3 + ci) * 224 + gy) * 224 + gx];
        sIn[ci][iy][ix] = v;
    }
    for (int idx = tid; idx < 300; idx += 256) {
        int c = idx / 75; int rem = idx - c * 75;
        sW[rem][c] = w[(cob * 4 + c) * 75 + rem];
    }
    __syncthreads();

    ull acc01 = 0, acc23 = 0;
    const int ty = threadIdx.y, tx = threadIdx.x;
#pragma unroll
    for (int ci = 0; ci < 3; ci++)
#pragma unroll
        for (int ky = 0; ky < 5; ky++)
#pragma unroll
            for (int kx = 0; kx < 5; kx++) {
                float v = sIn[ci][ty * 2 + ky][tx * 2 + kx];
                ull vv = pack2(v, v);
                const ulonglong2 wv = *(const ulonglong2*)&sW[ci * 25 + ky * 5 + kx][0];
                ffma2(acc01, vv, wv.x);
                ffma2(acc23, vv, wv.y);
            }

    float a[4];
    unpack2(acc01, a[0], a[1]);
    unpack2(acc23, a[2], a[3]);
    const int oy = oy0 + ty, ox = ox0 + tx;   // 112 = 7*16, always in range
#pragma unroll
    for (int c = 0; c < 4; c++) {
        int co = cob * 4 + c;
        float v = a[c] + b[co];
        v = v > 0.f ? v : LEAK * v;
        g_c1[((n * 32 + co) * 112 + oy) * 112 + ox] = v;
    }
}

// ---------------------------------------------------------------------------
// conv2: g_c1(32,32,112,112) -> g_c2(32,64,56,56), k5 s2 p2, leaky
// block (16,8)=128 thr: 4 rows (ty+8s) x 16 co per thread. 32-row tile.
// ci chunks of 4. smem 45 KB. grid (4,2,32*4)
// inner step: 4 LDS + 4 LDS.128 + 32 FFMA2 (64 MACs)
// ---------------------------------------------------------------------------
__global__ void conv2_kernel(const float* __restrict__ w,
                             const float* __restrict__ b) {
    __shared__ float sIn[4][67][36];                  // 38592 B
    __shared__ __align__(16) float sW[100][16];       // [ci*25+k][co], 6400 B
    const int tid = threadIdx.y * 16 + threadIdx.x;
    const int n   = blockIdx.z >> 2;
    const int cob = blockIdx.z & 3;
    const int oy0 = blockIdx.y * 32, ox0 = blockIdx.x * 16;
    const int ih0 = oy0 * 2 - 2, iw0 = ox0 * 2 - 2;
    const int ty = threadIdx.y, tx = threadIdx.x;

    ull acc[4][8] = {};   // [spatial row s][co pair]
    for (int ci0 = 0; ci0 < 32; ci0 += 4) {
        __syncthreads();
#pragma unroll
        for (int ci = 0; ci < 4; ci++) {
            const float* src = g_c1 + ((size_t)(n * 32 + ci0 + ci) * 112) * 112;
            for (int idx = tid; idx < 67 * 35; idx += 128) {
                int iy = idx / 35, ix = idx - iy * 35;
                int gy = ih0 + iy, gx = iw0 + ix;
                float v = 0.f;
                if (gy >= 0 && gy < 112 && gx >= 0 && gx < 112)
                    v = src[gy * 112 + gx];
                sIn[ci][iy][ix] = v;
            }
        }
        for (int idx = tid; idx < 16 * 100; idx += 128) {
            int c = idx / 100; int rem = idx - c * 100;
            sW[rem][c] = w[((cob * 16 + c) * 32 + ci0) * 25 + rem];
        }
        __syncthreads();

#pragma unroll
        for (int ci = 0; ci < 4; ci++) {
#pragma unroll
            for (int ky = 0; ky < 5; ky++)
#pragma unroll
                for (int kx = 0; kx < 5; kx++) {
                    ull vd[4];
#pragma unroll
                    for (int s = 0; s < 4; s++) {
                        float v = sIn[ci][ty * 2 + s * 16 + ky][tx * 2 + kx];
                        vd[s] = pack2(v, v);
                    }
                    const float* wr = &sW[ci * 25 + ky * 5 + kx][0];
                    const ulonglong2 wp0 = *(const ulonglong2*)(wr + 0);
                    const ulonglong2 wp1 = *(const ulonglong2*)(wr + 4);
                    const ulonglong2 wp2 = *(const ulonglong2*)(wr + 8);
                    const ulonglong2 wp3 = *(const ulonglong2*)(wr + 12);
#pragma unroll
                    for (int s = 0; s < 4; s++) {
                        ffma2(acc[s][0], vd[s], wp0.x); ffma2(acc[s][1], vd[s], wp0.y);
                        ffma2(acc[s][2], vd[s], wp1.x); ffma2(acc[s][3], vd[s], wp1.y);
                        ffma2(acc[s][4], vd[s], wp2.x); ffma2(acc[s][5], vd[s], wp2.y);
                        ffma2(acc[s][6], vd[s], wp3.x); ffma2(acc[s][7], vd[s], wp3.y);
                    }
                }
        }
    }
#pragma unroll
    for (int s = 0; s < 4; s++) {
        const int oy = oy0 + ty + s * 8, ox = ox0 + tx;
        if (oy < 56 && ox < 56) {
            float a[16];
#pragma unroll
            for (int cp = 0; cp < 8; cp++)
                unpack2(acc[s][cp], a[cp * 2], a[cp * 2 + 1]);
#pragma unroll
            for (int c = 0; c < 16; c++) {
                int co = cob * 16 + c;
                float v = a[c] + b[co];
                v = v > 0.f ? v : LEAK * v;
                g_c2[((n * 64 + co) * 56 + oy) * 56 + ox] = v;
            }
        }
    }
}

// ---------------------------------------------------------------------------
// conv3: g_c2(32,64,56,56) -> g_c3(32,128,56,56), k3 s1 p1, leaky
// block (16,8)=128 thr: 4 rows (ty+8s) x 16 co per thread. 32-row tile.
// ci chunks of 8. smem 26.4 KB. grid (4,2,32*8)
// inner step: 4 LDS + 4 LDS.128 + 32 FFMA2 (64 MACs)
// ---------------------------------------------------------------------------
__global__ void conv3_kernel(const float* __restrict__ w,
                             const float* __restrict__ b) {
    __shared__ float sIn[8][34][20];                  // 21760 B
    __shared__ __align__(16) float sW[72][16];        // [ci*9+k][co], 4608 B
    const int tid = threadIdx.y * 16 + threadIdx.x;
    const int n   = blockIdx.z >> 3;
    const int cob = blockIdx.z & 7;
    const int oy0 = blockIdx.y * 32, ox0 = blockIdx.x * 16;
    const int ih0 = oy0 - 1, iw0 = ox0 - 1;
    const int ty = threadIdx.y, tx = threadIdx.x;

    ull acc[4][8] = {};
    for (int ci0 = 0; ci0 < 64; ci0 += 8) {
        __syncthreads();
#pragma unroll
        for (int ci = 0; ci < 8; ci++) {
            const float* src = g_c2 + ((size_t)(n * 64 + ci0 + ci) * 56) * 56;
            for (int idx = tid; idx < 34 * 18; idx += 128) {
                int iy = idx / 18, ix = idx - iy * 18;
                int gy = ih0 + iy, gx = iw0 + ix;
                float v = 0.f;
                if (gy >= 0 && gy < 56 && gx >= 0 && gx < 56)
                    v = src[gy * 56 + gx];
                sIn[ci][iy][ix] = v;
            }
        }
        for (int idx = tid; idx < 16 * 72; idx += 128) {
            int c = idx / 72; int rem = idx - c * 72;
            sW[rem][c] = w[((cob * 16 + c) * 64 + ci0) * 9 + rem];
        }
        __syncthreads();

#pragma unroll
        for (int ci = 0; ci < 8; ci++) {
#pragma unroll
            for (int ky = 0; ky < 3; ky++)
#pragma unroll
                for (int kx = 0; kx < 3; kx++) {
                    ull vd[4];
#pragma unroll
                    for (int s = 0; s < 4; s++) {
                        float v = sIn[ci][ty + s * 8 + ky][tx + kx];
                        vd[s] = pack2(v, v);
                    }
                    const float* wr = &sW[ci * 9 + ky * 3 + kx][0];
                    const ulonglong2 wp0 = *(const ulonglong2*)(wr + 0);
                    const ulonglong2 wp1 = *(const ulonglong2*)(wr + 4);
                    const ulonglong2 wp2 = *(const ulonglong2*)(wr + 8);
                    const ulonglong2 wp3 = *(const ulonglong2*)(wr + 12);
#pragma unroll
                    for (int s = 0; s < 4; s++) {
                        ffma2(acc[s][0], vd[s], wp0.x); ffma2(acc[s][1], vd[s], wp0.y);
                        ffma2(acc[s][2], vd[s], wp1.x); ffma2(acc[s][3], vd[s], wp1.y);
                        ffma2(acc[s][4], vd[s], wp2.x); ffma2(acc[s][5], vd[s], wp2.y);
                        ffma2(acc[s][6], vd[s], wp3.x); ffma2(acc[s][7], vd[s], wp3.y);
                    }
                }
        }
    }
#pragma unroll
    for (int s = 0; s < 4; s++) {
        const int oy = oy0 + ty + s * 8, ox = ox0 + tx;
        if (oy < 56 && ox < 56) {
            float a[16];
#pragma unroll
            for (int cp = 0; cp < 8; cp++)
                unpack2(acc[s][cp], a[cp * 2], a[cp * 2 + 1]);
#pragma unroll
            for (int c = 0; c < 16; c++) {
                int co = cob * 16 + c;
                float v = a[c] + b[co];
                v = v > 0.f ? v : LEAK * v;
                g_c3[((n * 128 + co) * 56 + oy) * 56 + ox] = v;
            }
        }
    }
}

// ---------------------------------------------------------------------------
// roi_setup: one thread per (b, roi, point) -> 4 gather indices + 4 weights.
// ---------------------------------------------------------------------------
__global__ void roi_setup_kernel(const float* __restrict__ ROI) {
    int t = blockIdx.x * 256 + threadIdx.x;
    if (t >= 32 * 32 * 100) return;
    int br = t / 100;           // b*32 + roi
    int p  = t - br * 100;      // i*10 + j
    const float* roi = ROI + br * 7;
    float cx = roi[0], cy = roi[1];
    float W1 = roi[2], W2 = roi[3], H1 = roi[4], H2 = roi[5];
    float psi = roi[6];
    float WHx = W1 + W2, WHy = H1 + H2;
    float ofx = (W1 - W2) * 0.5f, ofy = (H1 - H2) * 0.5f;
    float sn = sinf(psi), cs = cosf(psi);
    int i = p / 10, j = p - i * 10;
    float offj = ((float)j - 4.5f) / 10.0f;
    float offi = ((float)i - 4.5f) / 10.0f;
    float gx = offj * WHx - ofx;
    float gy = offi * WHy - ofy;
    float X = gx * cs + gy * sn + cx;   // ggi @ rotM, col 0
    float Y = -gx * sn + gy * cs + cy;  // col 1
    int x0 = (int)floorf(X), x1 = x0 + 1;
    int y0 = (int)floorf(Y), y1 = y0 + 1;
    x0 = min(max(x0, 0), 55); x1 = min(max(x1, 0), 55);
    y0 = min(max(y0, 0), 55); y1 = min(max(y1, 0), 55);
    float x0f = (float)x0, x1f = (float)x1;
    float y0f = (float)y0, y1f = (float)y1;
    float step = (x1f - x0f) * (y1f - y0f);
    step = fminf(fmaxf(step, 0.001f), 2.0f);
    float inv = 1.0f / step;
    float4 wt;
    wt.x = (x1f - X) * (y1f - Y) * inv;   // Ia = img[y0, x0]
    wt.y = (x1f - X) * (Y - y0f) * inv;   // Ib = img[y1, x0]
    wt.z = (X - x0f) * (y1f - Y) * inv;   // Ic = img[y0, x1]
    wt.w = (X - x0f) * (Y - y0f) * inv;   // Id = img[y1, x1]
    int4 ii;
    ii.x = y0 * 56 + x0;
    ii.y = y1 * 56 + x0;
    ii.z = y0 * 56 + x1;
    ii.w = y1 * 56 + x1;
    g_tabI[t] = ii;
    g_tabW[t] = wt;
}

// ---------------------------------------------------------------------------
// roi_gather: reference's raw reshape (C, R*100) -> (R, C, 100):
//   flat[b][r2][c2*100 + p] = bilinear(feat[b], ch=r2*4 + c2/32, roi=c2%32, p)
// ---------------------------------------------------------------------------
__global__ void roi_gather_kernel() {
    const int br2 = blockIdx.x;
    const int b = br2 >> 5, r2 = br2 & 31;
    const int tid = threadIdx.x;
    const float* featb = g_c3 + (size_t)b * 128 * 3136;
    float* outp = g_flat + (size_t)br2 * 12800;
    for (int idx = tid; idx < 12800; idx += 256) {
        int c2 = idx / 100; int p = idx - c2 * 100;
        int roi = c2 & 31;            // ROI actually sampled
        int ch  = r2 * 4 + (c2 >> 5); // channel actually sampled
        int te = (b * 32 + roi) * 100 + p;
        int4   I = g_tabI[te];
        float4 W = g_tabW[te];
        const float* f = featb + ch * 3136;
        outp[idx] = f[I.x] * W.x + f[I.y] * W.y + f[I.z] * W.z + f[I.w] * W.w;
    }
}

// ---------------------------------------------------------------------------
// FC split-K: part[kz] (1024,256) = g_flat[:, kz*6400:(kz+1)*6400] @ fc_w^T
// 64x64 tile, BK=16, 256 threads, 4m x 4n micro-tile. grid (4 n, 16 m, 2 kz)
// ---------------------------------------------------------------------------
__global__ void fc_kernel(const float* __restrict__ Bw) {
    __shared__ __align__(16) float As[16][68];
    __shared__ __align__(16) float Bs[16][68];
    const int tid = threadIdx.x;
    const int m0 = blockIdx.y * 64, n0 = blockIdx.x * 64;
    const int k0base = blockIdx.z * 6400;
    const int lm = tid >> 2, lk = (tid & 3) * 4;
    const int ty = tid >> 4, tx = tid & 15;

    const float* Aptr = g_flat + (size_t)(m0 + lm) * 12800 + k0base + lk;
    const float* Bptr = Bw + (size_t)(n0 + lm) * 12800 + k0base + lk;

    ull acc[4][2] = {};
    for (int k0 = 0; k0 < 6400; k0 += 16) {
        float4 av = *(const float4*)(Aptr + k0);
        float4 bv = *(const float4*)(Bptr + k0);
        As[lk + 0][lm] = av.x; As[lk + 1][lm] = av.y;
        As[lk + 2][lm] = av.z; As[lk + 3][lm] = av.w;
        Bs[lk + 0][lm] = bv.x; Bs[lk + 1][lm] = bv.y;
        Bs[lk + 2][lm] = bv.z; Bs[lk + 3][lm] = bv.w;
        __syncthreads();
#pragma unroll
        for (int kk = 0; kk < 16; kk++) {
            const float4 af = *(const float4*)&As[kk][ty * 4];
            const ulonglong2 bp = *(const ulonglong2*)&Bs[kk][tx * 4];
            ull a0 = pack2(af.x, af.x);
            ull a1 = pack2(af.y, af.y);
            ull a2 = pack2(af.z, af.z);
            ull a3 = pack2(af.w, af.w);
            ffma2(acc[0][0], a0, bp.x); ffma2(acc[0][1], a0, bp.y);
            ffma2(acc[1][0], a1, bp.x); ffma2(acc[1][1], a1, bp.y);
            ffma2(acc[2][0], a2, bp.x); ffma2(acc[2][1], a2, bp.y);
            ffma2(acc[3][0], a3, bp.x); ffma2(acc[3][1], a3, bp.y);
        }
        __syncthreads();
    }
    float* part = g_part + (size_t)blockIdx.z * 1024 * 256;
#pragma unroll
    for (int i = 0; i < 4; i++) {
        int m = m0 + ty * 4 + i;
        float r[4];
        unpack2(acc[i][0], r[0], r[1]);
        unpack2(acc[i][1], r[2], r[3]);
#pragma unroll
        for (int j = 0; j < 4; j++) {
            int nn = n0 + tx * 4 + j;
            part[m * 256 + nn] = r[j];
        }
    }
}

// out = part0 + part1 + bias  (deterministic fixed-order reduce)
__global__ void fc_reduce_kernel(const float* __restrict__ bias,
                                 float* __restrict__ out) {
    int idx = blockIdx.x * 256 + threadIdx.x;   // 1024*256 total
    int nn = idx & 255;
    out[idx] = g_part[idx] + g_part[idx + 1024 * 256] + bias[nn];
}

// ---------------------------------------------------------------------------
extern "C" void kernel_launch(void* const* d_in, const int* in_sizes, int n_in,
                              void* d_out, int out_size) {
    const float* x   = (const float*)d_in[0];
    const float* ROI = (const float*)d_in[1];
    const float* w1  = (const float*)d_in[2];
    const float* b1  = (const float*)d_in[3];
    const float* w2  = (const float*)d_in[4];
    const float* b2  = (const float*)d_in[5];
    const float* w3  = (const float*)d_in[6];
    const float* b3  = (const float*)d_in[7];
    const float* fcw = (const float*)d_in[8];
    const float* fcb = (const float*)d_in[9];
    float* out = (float*)d_out;

    warm_kernel<<<1, 128>>>();   // shifts ncu capture (launch idx 3) onto conv3
    conv1_kernel<<<dim3(7, 7, 32 * 8),  dim3(16, 16)>>>(x, w1, b1);
    conv2_kernel<<<dim3(4, 2, 32 * 4),  dim3(16, 8)>>>(w2, b2);
    conv3_kernel<<<dim3(4, 2, 32 * 8),  dim3(16, 8)>>>(w3, b3);
    roi_setup_kernel<<<(32 * 32 * 100 + 255) / 256, 256>>>(ROI);
    roi_gather_kernel<<<1024, 256>>>();
    fc_kernel<<<dim3(4, 16, 2), 256>>>(fcw);
    fc_reduce_kernel<<<1024, 256>>>(fcb, out);
}

// round 15
// speedup vs baseline: 1.0971x; 1.0971x over previous
#include <cuda_runtime.h>

#define LEAK 0.2f

// Scratch (allocation-free rule: __device__ globals)
__device__ float g_c1[32u*32u*112u*112u];   // 51.4 MB
__device__ float g_c2[32u*64u*56u*56u];     // 25.7 MB
__device__ float g_c3[32u*128u*56u*56u];    // 51.4 MB
__device__ float g_flat[32u*32u*12800u];    // 52.4 MB
__device__ float g_part[2u*1024u*256u];     // FC split-K partials (2 MB)
__device__ int4   g_tabI[32*32*100];        // bilinear gather indices
__device__ float4 g_tabW[32*32*100];        // bilinear weights

typedef unsigned long long ull;

// ---- packed f32x2 helpers (sm_103a; ptxas never emits FFMA2 from C++) ----
__device__ __forceinline__ ull pack2(float x, float y) {
    ull r; asm("mov.b64 %0,{%1,%2};" : "=l"(r) : "f"(x), "f"(y)); return r;
}
__device__ __forceinline__ void unpack2(ull v, float& x, float& y) {
    asm("mov.b64 {%0,%1},%2;" : "=f"(x), "=f"(y) : "l"(v));
}
__device__ __forceinline__ void ffma2(ull& d, ull a, ull b) {
    asm("fma.rn.f32x2 %0,%1,%2,%0;" : "+l"(d) : "l"(a), "l"(b));
}

// no-op: shifts ncu's captured-launch index onto conv3
__global__ void warm_kernel() {}

// ---------------------------------------------------------------------------
// conv1: x(32,3,224,224) -> g_c1(32,32,112,112), k5 s2 p2, leaky
// block (16,16): 16x16 spatial, 4 co per thread (2 f32x2 accs). grid (7,7,256)
// ---------------------------------------------------------------------------
__global__ void conv1_kernel(const float* __restrict__ x,
                             const float* __restrict__ w,
                             const float* __restrict__ b) {
    __shared__ float sIn[3][35][36];
    __shared__ __align__(16) float sW[75][4];   // [ci*25+k][co]
    const int tid = threadIdx.y * 16 + threadIdx.x;
    const int n   = blockIdx.z >> 3;
    const int cob = blockIdx.z & 7;
    const int oy0 = blockIdx.y * 16, ox0 = blockIdx.x * 16;
    const int ih0 = oy0 * 2 - 2, iw0 = ox0 * 2 - 2;

    for (int idx = tid; idx < 3 * 35 * 35; idx += 256) {
        int ci = idx / 1225; int rem = idx - ci * 1225;
        int iy = rem / 35, ix = rem - iy * 35;
        int gy = ih0 + iy, gx = iw0 + ix;
        float v = 0.f;
        if (gy >= 0 && gy < 224 && gx >= 0 && gx < 224)
            v = x[((n * 3 + ci) * 224 + gy) * 224 + gx];
        sIn[ci][iy][ix] = v;
    }
    for (int idx = tid; idx < 300; idx += 256) {
        int c = idx / 75; int rem = idx - c * 75;
        sW[rem][c] = w[(cob * 4 + c) * 75 + rem];
    }
    __syncthreads();

    ull acc01 = 0, acc23 = 0;
    const int ty = threadIdx.y, tx = threadIdx.x;
#pragma unroll
    for (int ci = 0; ci < 3; ci++)
#pragma unroll
        for (int ky = 0; ky < 5; ky++)
#pragma unroll
            for (int kx = 0; kx < 5; kx++) {
                float v = sIn[ci][ty * 2 + ky][tx * 2 + kx];
                ull vv = pack2(v, v);
                const ulonglong2 wv = *(const ulonglong2*)&sW[ci * 25 + ky * 5 + kx][0];
                ffma2(acc01, vv, wv.x);
                ffma2(acc23, vv, wv.y);
            }

    float a[4];
    unpack2(acc01, a[0], a[1]);
    unpack2(acc23, a[2], a[3]);
    const int oy = oy0 + ty, ox = ox0 + tx;   // 112 = 7*16, always in range
#pragma unroll
    for (int c = 0; c < 4; c++) {
        int co = cob * 4 + c;
        float v = a[c] + b[co];
        v = v > 0.f ? v : LEAK * v;
        g_c1[((n * 32 + co) * 112 + oy) * 112 + ox] = v;
    }
}

// ---------------------------------------------------------------------------
// conv2: g_c1(32,32,112,112) -> g_c2(32,64,56,56), k5 s2 p2, leaky
// block (16,8)=128 thr: 2 rows (ty, ty+8) x 16 co per thread.
// ci chunks of 4. grid (4,4,32*4)   [R12 config]
// ---------------------------------------------------------------------------
__global__ void conv2_kernel(const float* __restrict__ w,
                             const float* __restrict__ b) {
    __shared__ float sIn[4][35][36];                  // 20160 B
    __shared__ __align__(16) float sW[100][16];       // [ci*25+k][co], 6400 B
    const int tid = threadIdx.y * 16 + threadIdx.x;
    const int n   = blockIdx.z >> 2;
    const int cob = blockIdx.z & 3;
    const int oy0 = blockIdx.y * 16, ox0 = blockIdx.x * 16;
    const int ih0 = oy0 * 2 - 2, iw0 = ox0 * 2 - 2;
    const int ty = threadIdx.y, tx = threadIdx.x;

    ull acc[2][8] = {};   // [spatial row][co pair]
    for (int ci0 = 0; ci0 < 32; ci0 += 4) {
        __syncthreads();
        for (int idx = tid; idx < 4 * 35 * 35; idx += 128) {
            int ci = idx / 1225; int rem = idx - ci * 1225;
            int iy = rem / 35, ix = rem - iy * 35;
            int gy = ih0 + iy, gx = iw0 + ix;
            float v = 0.f;
            if (gy >= 0 && gy < 112 && gx >= 0 && gx < 112)
                v = g_c1[((n * 32 + ci0 + ci) * 112 + gy) * 112 + gx];
            sIn[ci][iy][ix] = v;
        }
        for (int idx = tid; idx < 16 * 100; idx += 128) {
            int c = idx / 100; int rem = idx - c * 100;
            sW[rem][c] = w[((cob * 16 + c) * 32 + ci0) * 25 + rem];
        }
        __syncthreads();

#pragma unroll
        for (int ci = 0; ci < 4; ci++) {
#pragma unroll
            for (int ky = 0; ky < 5; ky++)
#pragma unroll
                for (int kx = 0; kx < 5; kx++) {
                    float v0 = sIn[ci][ty * 2 + ky][tx * 2 + kx];
                    float v1 = sIn[ci][ty * 2 + 16 + ky][tx * 2 + kx];
                    ull v0d = pack2(v0, v0);
                    ull v1d = pack2(v1, v1);
                    const float* wr = &sW[ci * 25 + ky * 5 + kx][0];
                    const ulonglong2 wp0 = *(const ulonglong2*)(wr + 0);
                    const ulonglong2 wp1 = *(const ulonglong2*)(wr + 4);
                    const ulonglong2 wp2 = *(const ulonglong2*)(wr + 8);
                    const ulonglong2 wp3 = *(const ulonglong2*)(wr + 12);
                    ffma2(acc[0][0], v0d, wp0.x); ffma2(acc[0][1], v0d, wp0.y);
                    ffma2(acc[0][2], v0d, wp1.x); ffma2(acc[0][3], v0d, wp1.y);
                    ffma2(acc[0][4], v0d, wp2.x); ffma2(acc[0][5], v0d, wp2.y);
                    ffma2(acc[0][6], v0d, wp3.x); ffma2(acc[0][7], v0d, wp3.y);
                    ffma2(acc[1][0], v1d, wp0.x); ffma2(acc[1][1], v1d, wp0.y);
                    ffma2(acc[1][2], v1d, wp1.x); ffma2(acc[1][3], v1d, wp1.y);
                    ffma2(acc[1][4], v1d, wp2.x); ffma2(acc[1][5], v1d, wp2.y);
                    ffma2(acc[1][6], v1d, wp3.x); ffma2(acc[1][7], v1d, wp3.y);
                }
        }
    }
#pragma unroll
    for (int s = 0; s < 2; s++) {
        const int oy = oy0 + ty + s * 8, ox = ox0 + tx;
        if (oy < 56 && ox < 56) {
            float a[16];
#pragma unroll
            for (int cp = 0; cp < 8; cp++)
                unpack2(acc[s][cp], a[cp * 2], a[cp * 2 + 1]);
#pragma unroll
            for (int c = 0; c < 16; c++) {
                int co = cob * 16 + c;
                float v = a[c] + b[co];
                v = v > 0.f ? v : LEAK * v;
                g_c2[((n * 64 + co) * 56 + oy) * 56 + ox] = v;
            }
        }
    }
}

// ---------------------------------------------------------------------------
// conv3: g_c2(32,64,56,56) -> g_c3(32,128,56,56), k3 s1 p1, leaky
// block (16,8)=128 thr: 2x2 consecutive output patch x 8 co per thread.
// tile 16 rows x 32 cols. acc = 16 ull (32 regs). ci chunks of 8.
// per ci: 8 LDS.64 values (4x4 patch) + 16 pack MOVs + 18 LDS.128 weights
//         + 144 FFMA2.  grid (2,4,32*16) = 4096 blocks, smem ~23 KB.
// ---------------------------------------------------------------------------
__global__ void conv3_kernel(const float* __restrict__ w,
                             const float* __restrict__ b) {
    __shared__ float sIn[8][18][36];                  // 20736 B
    __shared__ __align__(16) float sW[72][8];         // [ci*9+k][co], 2304 B
    const int tid = threadIdx.y * 16 + threadIdx.x;
    const int n   = blockIdx.z >> 4;
    const int cob = blockIdx.z & 15;
    const int oy0 = blockIdx.y * 16, ox0 = blockIdx.x * 32;
    const int ih0 = oy0 - 1, iw0 = ox0 - 1;
    const int ty = threadIdx.y, tx = threadIdx.x;

    ull acc[2][2][4] = {};   // [row s][col c][co pair]
    for (int ci0 = 0; ci0 < 64; ci0 += 8) {
        __syncthreads();
#pragma unroll
        for (int ci = 0; ci < 8; ci++) {
            const float* src = g_c2 + ((size_t)(n * 64 + ci0 + ci) * 56) * 56;
            for (int idx = tid; idx < 18 * 34; idx += 128) {
                int iy = idx / 34, ix = idx - iy * 34;
                int gy = ih0 + iy, gx = iw0 + ix;
                float v = 0.f;
                if (gy >= 0 && gy < 56 && gx >= 0 && gx < 56)
                    v = src[gy * 56 + gx];
                sIn[ci][iy][ix] = v;
            }
        }
        for (int idx = tid; idx < 8 * 72; idx += 128) {
            int c = idx / 72; int rem = idx - c * 72;
            sW[rem][c] = w[((cob * 8 + c) * 64 + ci0) * 9 + rem];
        }
        __syncthreads();

#pragma unroll
        for (int ci = 0; ci < 8; ci++) {
            // 4x4 input patch: rows ty*2..ty*2+3, cols tx*2..tx*2+3
            ull pk[4][4];
#pragma unroll
            for (int r = 0; r < 4; r++) {
                float2 a = *(const float2*)&sIn[ci][ty * 2 + r][tx * 2];
                float2 bq = *(const float2*)&sIn[ci][ty * 2 + r][tx * 2 + 2];
                pk[r][0] = pack2(a.x, a.x);
                pk[r][1] = pack2(a.y, a.y);
                pk[r][2] = pack2(bq.x, bq.x);
                pk[r][3] = pack2(bq.y, bq.y);
            }
#pragma unroll
            for (int ky = 0; ky < 3; ky++)
#pragma unroll
                for (int kx = 0; kx < 3; kx++) {
                    const float* wr = &sW[ci * 9 + ky * 3 + kx][0];
                    const ulonglong2 wp0 = *(const ulonglong2*)(wr + 0);
                    const ulonglong2 wp1 = *(const ulonglong2*)(wr + 4);
#pragma unroll
                    for (int s = 0; s < 2; s++)
#pragma unroll
                        for (int c = 0; c < 2; c++) {
                            ull v = pk[s + ky][c + kx];
                            ffma2(acc[s][c][0], v, wp0.x);
                            ffma2(acc[s][c][1], v, wp0.y);
                            ffma2(acc[s][c][2], v, wp1.x);
                            ffma2(acc[s][c][3], v, wp1.y);
                        }
                }
        }
    }
#pragma unroll
    for (int s = 0; s < 2; s++) {
#pragma unroll
        for (int c = 0; c < 2; c++) {
            const int oy = oy0 + ty * 2 + s, ox = ox0 + tx * 2 + c;
            if (oy < 56 && ox < 56) {
                float a[8];
#pragma unroll
                for (int cp = 0; cp < 4; cp++)
                    unpack2(acc[s][c][cp], a[cp * 2], a[cp * 2 + 1]);
#pragma unroll
                for (int k = 0; k < 8; k++) {
                    int co = cob * 8 + k;
                    float v = a[k] + b[co];
                    v = v > 0.f ? v : LEAK * v;
                    g_c3[((n * 128 + co) * 56 + oy) * 56 + ox] = v;
                }
            }
        }
    }
}

// ---------------------------------------------------------------------------
// roi_setup: one thread per (b, roi, point) -> 4 gather indices + 4 weights.
// ---------------------------------------------------------------------------
__global__ void roi_setup_kernel(const float* __restrict__ ROI) {
    int t = blockIdx.x * 256 + threadIdx.x;
    if (t >= 32 * 32 * 100) return;
    int br = t / 100;           // b*32 + roi
    int p  = t - br * 100;      // i*10 + j
    const float* roi = ROI + br * 7;
    float cx = roi[0], cy = roi[1];
    float W1 = roi[2], W2 = roi[3], H1 = roi[4], H2 = roi[5];
    float psi = roi[6];
    float WHx = W1 + W2, WHy = H1 + H2;
    float ofx = (W1 - W2) * 0.5f, ofy = (H1 - H2) * 0.5f;
    float sn = sinf(psi), cs = cosf(psi);
    int i = p / 10, j = p - i * 10;
    float offj = ((float)j - 4.5f) / 10.0f;
    float offi = ((float)i - 4.5f) / 10.0f;
    float gx = offj * WHx - ofx;
    float gy = offi * WHy - ofy;
    float X = gx * cs + gy * sn + cx;   // ggi @ rotM, col 0
    float Y = -gx * sn + gy * cs + cy;  // col 1
    int x0 = (int)floorf(X), x1 = x0 + 1;
    int y0 = (int)floorf(Y), y1 = y0 + 1;
    x0 = min(max(x0, 0), 55); x1 = min(max(x1, 0), 55);
    y0 = min(max(y0, 0), 55); y1 = min(max(y1, 0), 55);
    float x0f = (float)x0, x1f = (float)x1;
    float y0f = (float)y0, y1f = (float)y1;
    float step = (x1f - x0f) * (y1f - y0f);
    step = fminf(fmaxf(step, 0.001f), 2.0f);
    float inv = 1.0f / step;
    float4 wt;
    wt.x = (x1f - X) * (y1f - Y) * inv;   // Ia = img[y0, x0]
    wt.y = (x1f - X) * (Y - y0f) * inv;   // Ib = img[y1, x0]
    wt.z = (X - x0f) * (y1f - Y) * inv;   // Ic = img[y0, x1]
    wt.w = (X - x0f) * (Y - y0f) * inv;   // Id = img[y1, x1]
    int4 ii;
    ii.x = y0 * 56 + x0;
    ii.y = y1 * 56 + x0;
    ii.z = y0 * 56 + x1;
    ii.w = y1 * 56 + x1;
    g_tabI[t] = ii;
    g_tabW[t] = wt;
}

// ---------------------------------------------------------------------------
// roi_gather: reference's raw reshape (C, R*100) -> (R, C, 100):
//   flat[b][r2][c2*100 + p] = bilinear(feat[b], ch=r2*4 + c2/32, roi=c2%32, p)
// ---------------------------------------------------------------------------
__global__ void roi_gather_kernel() {
    const int br2 = blockIdx.x;
    const int b = br2 >> 5, r2 = br2 & 31;
    const int tid = threadIdx.x;
    const float* featb = g_c3 + (size_t)b * 128 * 3136;
    float* outp = g_flat + (size_t)br2 * 12800;
    for (int idx = tid; idx < 12800; idx += 256) {
        int c2 = idx / 100; int p = idx - c2 * 100;
        int roi = c2 & 31;            // ROI actually sampled
        int ch  = r2 * 4 + (c2 >> 5); // channel actually sampled
        int te = (b * 32 + roi) * 100 + p;
        int4   I = g_tabI[te];
        float4 W = g_tabW[te];
        const float* f = featb + ch * 3136;
        outp[idx] = f[I.x] * W.x + f[I.y] * W.y + f[I.z] * W.z + f[I.w] * W.w;
    }
}

// ---------------------------------------------------------------------------
// FC split-K: part[kz] (1024,256) = g_flat[:, kz*6400:(kz+1)*6400] @ fc_w^T
// 64x64 tile, BK=16, 256 threads, 4m x 4n micro-tile. grid (4 n, 16 m, 2 kz)
// ---------------------------------------------------------------------------
__global__ void fc_kernel(const float* __restrict__ Bw) {
    __shared__ __align__(16) float As[16][68];
    __shared__ __align__(16) float Bs[16][68];
    const int tid = threadIdx.x;
    const int m0 = blockIdx.y * 64, n0 = blockIdx.x * 64;
    const int k0base = blockIdx.z * 6400;
    const int lm = tid >> 2, lk = (tid & 3) * 4;
    const int ty = tid >> 4, tx = tid & 15;

    const float* Aptr = g_flat + (size_t)(m0 + lm) * 12800 + k0base + lk;
    const float* Bptr = Bw + (size_t)(n0 + lm) * 12800 + k0base + lk;

    ull acc[4][2] = {};
    for (int k0 = 0; k0 < 6400; k0 += 16) {
        float4 av = *(const float4*)(Aptr + k0);
        float4 bv = *(const float4*)(Bptr + k0);
        As[lk + 0][lm] = av.x; As[lk + 1][lm] = av.y;
        As[lk + 2][lm] = av.z; As[lk + 3][lm] = av.w;
        Bs[lk + 0][lm] = bv.x; Bs[lk + 1][lm] = bv.y;
        Bs[lk + 2][lm] = bv.z; Bs[lk + 3][lm] = bv.w;
        __syncthreads();
#pragma unroll
        for (int kk = 0; kk < 16; kk++) {
            const float4 af = *(const float4*)&As[kk][ty * 4];
            const ulonglong2 bp = *(const ulonglong2*)&Bs[kk][tx * 4];
            ull a0 = pack2(af.x, af.x);
            ull a1 = pack2(af.y, af.y);
            ull a2 = pack2(af.z, af.z);
            ull a3 = pack2(af.w, af.w);
            ffma2(acc[0][0], a0, bp.x); ffma2(acc[0][1], a0, bp.y);
            ffma2(acc[1][0], a1, bp.x); ffma2(acc[1][1], a1, bp.y);
            ffma2(acc[2][0], a2, bp.x); ffma2(acc[2][1], a2, bp.y);
            ffma2(acc[3][0], a3, bp.x); ffma2(acc[3][1], a3, bp.y);
        }
        __syncthreads();
    }
    float* part = g_part + (size_t)blockIdx.z * 1024 * 256;
#pragma unroll
    for (int i = 0; i < 4; i++) {
        int m = m0 + ty * 4 + i;
        float r[4];
        unpack2(acc[i][0], r[0], r[1]);
        unpack2(acc[i][1], r[2], r[3]);
#pragma unroll
        for (int j = 0; j < 4; j++) {
            int nn = n0 + tx * 4 + j;
            part[m * 256 + nn] = r[j];
        }
    }
}

// out = part0 + part1 + bias  (deterministic fixed-order reduce)
__global__ void fc_reduce_kernel(const float* __restrict__ bias,
                                 float* __restrict__ out) {
    int idx = blockIdx.x * 256 + threadIdx.x;   // 1024*256 total
    int nn = idx & 255;
    out[idx] = g_part[idx] + g_part[idx + 1024 * 256] + bias[nn];
}

// ---------------------------------------------------------------------------
extern "C" void kernel_launch(void* const* d_in, const int* in_sizes, int n_in,
                              void* d_out, int out_size) {
    const float* x   = (const float*)d_in[0];
    const float* ROI = (const float*)d_in[1];
    const float* w1  = (const float*)d_in[2];
    const float* b1  = (const float*)d_in[3];
    const float* w2  = (const float*)d_in[4];
    const float* b2  = (const float*)d_in[5];
    const float* w3  = (const float*)d_in[6];
    const float* b3  = (const float*)d_in[7];
    const float* fcw = (const float*)d_in[8];
    const float* fcb = (const float*)d_in[9];
    float* out = (float*)d_out;

    warm_kernel<<<1, 128>>>();   // shifts ncu capture (launch idx 3) onto conv3
    conv1_kernel<<<dim3(7, 7, 32 * 8),  dim3(16, 16)>>>(x, w1, b1);
    conv2_kernel<<<dim3(4, 4, 32 * 4),  dim3(16, 8)>>>(w2, b2);
    conv3_kernel<<<dim3(2, 4, 32 * 16), dim3(16, 8)>>>(w3, b3);
    roi_setup_kernel<<<(32 * 32 * 100 + 255) / 256, 256>>>(ROI);
    roi_gather_kernel<<<1024, 256>>>();
    fc_kernel<<<dim3(4, 16, 2), 256>>>(fcw);
    fc_reduce_kernel<<<1024, 256>>>(fcb, out);
}

// round 16
// speedup vs baseline: 1.1320x; 1.0318x over previous
#include <cuda_runtime.h>

#define LEAK 0.2f

// Scratch (allocation-free rule: __device__ globals)
__device__ float g_c1[32u*32u*112u*112u];   // 51.4 MB
__device__ float g_c2[32u*64u*56u*56u];     // 25.7 MB
__device__ float g_c3[32u*128u*56u*56u];    // 51.4 MB
__device__ float g_flat[32u*32u*12800u];    // 52.4 MB
__device__ float g_part[2u*1024u*256u];     // FC split-K partials (2 MB)
__device__ int4   g_tabI[32*32*100];        // bilinear gather indices
__device__ float4 g_tabW[32*32*100];        // bilinear weights

typedef unsigned long long ull;

// ---- packed f32x2 helpers (sm_103a; ptxas never emits FFMA2 from C++) ----
__device__ __forceinline__ ull pack2(float x, float y) {
    ull r; asm("mov.b64 %0,{%1,%2};" : "=l"(r) : "f"(x), "f"(y)); return r;
}
__device__ __forceinline__ void unpack2(ull v, float& x, float& y) {
    asm("mov.b64 {%0,%1},%2;" : "=f"(x), "=f"(y) : "l"(v));
}
__device__ __forceinline__ void ffma2(ull& d, ull a, ull b) {
    asm("fma.rn.f32x2 %0,%1,%2,%0;" : "+l"(d) : "l"(a), "l"(b));
}

// no-op: shifts ncu's captured-launch index onto conv3
__global__ void warm_kernel() {}

// ---------------------------------------------------------------------------
// conv1: x(32,3,224,224) -> g_c1(32,32,112,112), k5 s2 p2, leaky
// block (16,16): 16x16 spatial, 4 co per thread (2 f32x2 accs). grid (7,7,256)
// ---------------------------------------------------------------------------
__global__ void conv1_kernel(const float* __restrict__ x,
                             const float* __restrict__ w,
                             const float* __restrict__ b) {
    __shared__ float sIn[3][35][36];
    __shared__ __align__(16) float sW[75][4];   // [ci*25+k][co]
    const int tid = threadIdx.y * 16 + threadIdx.x;
    const int n   = blockIdx.z >> 3;
    const int cob = blockIdx.z & 7;
    const int oy0 = blockIdx.y * 16, ox0 = blockIdx.x * 16;
    const int ih0 = oy0 * 2 - 2, iw0 = ox0 * 2 - 2;

    for (int idx = tid; idx < 3 * 35 * 35; idx += 256) {
        int ci = idx / 1225; int rem = idx - ci * 1225;
        int iy = rem / 35, ix = rem - iy * 35;
        int gy = ih0 + iy, gx = iw0 + ix;
        float v = 0.f;
        if (gy >= 0 && gy < 224 && gx >= 0 && gx < 224)
            v = x[((n * 3 + ci) * 224 + gy) * 224 + gx];
        sIn[ci][iy][ix] = v;
    }
    for (int idx = tid; idx < 300; idx += 256) {
        int c = idx / 75; int rem = idx - c * 75;
        sW[rem][c] = w[(cob * 4 + c) * 75 + rem];
    }
    __syncthreads();

    ull acc01 = 0, acc23 = 0;
    const int ty = threadIdx.y, tx = threadIdx.x;
#pragma unroll
    for (int ci = 0; ci < 3; ci++)
#pragma unroll
        for (int ky = 0; ky < 5; ky++)
#pragma unroll
            for (int kx = 0; kx < 5; kx++) {
                float v = sIn[ci][ty * 2 + ky][tx * 2 + kx];
                ull vv = pack2(v, v);
                const ulonglong2 wv = *(const ulonglong2*)&sW[ci * 25 + ky * 5 + kx][0];
                ffma2(acc01, vv, wv.x);
                ffma2(acc23, vv, wv.y);
            }

    float a[4];
    unpack2(acc01, a[0], a[1]);
    unpack2(acc23, a[2], a[3]);
    const int oy = oy0 + ty, ox = ox0 + tx;   // 112 = 7*16, always in range
#pragma unroll
    for (int c = 0; c < 4; c++) {
        int co = cob * 4 + c;
        float v = a[c] + b[co];
        v = v > 0.f ? v : LEAK * v;
        g_c1[((n * 32 + co) * 112 + oy) * 112 + ox] = v;
    }
}

// ---------------------------------------------------------------------------
// conv2: g_c1(32,32,112,112) -> g_c2(32,64,56,56), k5 s2 p2, leaky
// block (16,16)=256 thr, 2 warpgroups x 16 co on a SHARED staged tile.
// Each 128-thr wg: 2 rows (sty, sty+8) x 16 co. ci chunks of 4.
// grid (4,4,32*2). smem: 20160 + 12800 = 33 KB.
// ---------------------------------------------------------------------------
__global__ void conv2_kernel(const float* __restrict__ w,
                             const float* __restrict__ b) {
    __shared__ float sIn[4][35][36];                  // 20160 B (shared by both wgs)
    __shared__ __align__(16) float sW[100][32];       // [ci*25+k][co], 12800 B
    const int tid = threadIdx.y * 16 + threadIdx.x;
    const int wg  = tid >> 7;                         // 0/1: co half
    const int wtid = tid & 127;
    const int sty = wtid >> 4, stx = wtid & 15;
    const int n    = blockIdx.z >> 1;
    const int cobg = blockIdx.z & 1;                  // 2 groups of 32 co
    const int oy0 = blockIdx.y * 16, ox0 = blockIdx.x * 16;
    const int ih0 = oy0 * 2 - 2, iw0 = ox0 * 2 - 2;

    ull acc[2][8] = {};   // [spatial row][co pair]
    for (int ci0 = 0; ci0 < 32; ci0 += 4) {
        __syncthreads();
        for (int idx = tid; idx < 4 * 35 * 35; idx += 256) {
            int ci = idx / 1225; int rem = idx - ci * 1225;
            int iy = rem / 35, ix = rem - iy * 35;
            int gy = ih0 + iy, gx = iw0 + ix;
            float v = 0.f;
            if (gy >= 0 && gy < 112 && gx >= 0 && gx < 112)
                v = g_c1[((n * 32 + ci0 + ci) * 112 + gy) * 112 + gx];
            sIn[ci][iy][ix] = v;
        }
        for (int idx = tid; idx < 32 * 100; idx += 256) {
            int c = idx / 100; int rem = idx - c * 100;
            sW[rem][c] = w[((cobg * 32 + c) * 32 + ci0) * 25 + rem];
        }
        __syncthreads();

#pragma unroll
        for (int ci = 0; ci < 4; ci++) {
#pragma unroll
            for (int ky = 0; ky < 5; ky++)
#pragma unroll
                for (int kx = 0; kx < 5; kx++) {
                    float v0 = sIn[ci][sty * 2 + ky][stx * 2 + kx];
                    float v1 = sIn[ci][sty * 2 + 16 + ky][stx * 2 + kx];
                    ull v0d = pack2(v0, v0);
                    ull v1d = pack2(v1, v1);
                    const float* wr = &sW[ci * 25 + ky * 5 + kx][wg * 16];
                    const ulonglong2 wp0 = *(const ulonglong2*)(wr + 0);
                    const ulonglong2 wp1 = *(const ulonglong2*)(wr + 4);
                    const ulonglong2 wp2 = *(const ulonglong2*)(wr + 8);
                    const ulonglong2 wp3 = *(const ulonglong2*)(wr + 12);
                    ffma2(acc[0][0], v0d, wp0.x); ffma2(acc[0][1], v0d, wp0.y);
                    ffma2(acc[0][2], v0d, wp1.x); ffma2(acc[0][3], v0d, wp1.y);
                    ffma2(acc[0][4], v0d, wp2.x); ffma2(acc[0][5], v0d, wp2.y);
                    ffma2(acc[0][6], v0d, wp3.x); ffma2(acc[0][7], v0d, wp3.y);
                    ffma2(acc[1][0], v1d, wp0.x); ffma2(acc[1][1], v1d, wp0.y);
                    ffma2(acc[1][2], v1d, wp1.x); ffma2(acc[1][3], v1d, wp1.y);
                    ffma2(acc[1][4], v1d, wp2.x); ffma2(acc[1][5], v1d, wp2.y);
                    ffma2(acc[1][6], v1d, wp3.x); ffma2(acc[1][7], v1d, wp3.y);
                }
        }
    }
#pragma unroll
    for (int s = 0; s < 2; s++) {
        const int oy = oy0 + sty + s * 8, ox = ox0 + stx;
        if (oy < 56 && ox < 56) {
            float a[16];
#pragma unroll
            for (int cp = 0; cp < 8; cp++)
                unpack2(acc[s][cp], a[cp * 2], a[cp * 2 + 1]);
#pragma unroll
            for (int c = 0; c < 16; c++) {
                int co = cobg * 32 + wg * 16 + c;
                float v = a[c] + b[co];
                v = v > 0.f ? v : LEAK * v;
                g_c2[((n * 64 + co) * 56 + oy) * 56 + ox] = v;
            }
        }
    }
}

// ---------------------------------------------------------------------------
// conv3: g_c2(32,64,56,56) -> g_c3(32,128,56,56), k3 s1 p1, leaky
// block (16,16)=256 thr, 2 warpgroups x 8 co on a SHARED staged tile.
// Each 128-thr wg: 2x2 output patch x 8 co. tile 16 rows x 32 cols.
// ci chunks of 8. grid (2,4,32*8). smem: 20736 + 4608 = 25.3 KB.
// ---------------------------------------------------------------------------
__global__ void conv3_kernel(const float* __restrict__ w,
                             const float* __restrict__ b) {
    __shared__ float sIn[8][18][36];                  // 20736 B (shared)
    __shared__ __align__(16) float sW[72][16];        // [ci*9+k][co], 4608 B
    const int tid = threadIdx.y * 16 + threadIdx.x;
    const int wg  = tid >> 7;                         // 0/1: co half
    const int wtid = tid & 127;
    const int sty = wtid >> 4, stx = wtid & 15;
    const int n    = blockIdx.z >> 3;
    const int cobg = blockIdx.z & 7;                  // 8 groups of 16 co
    const int oy0 = blockIdx.y * 16, ox0 = blockIdx.x * 32;
    const int ih0 = oy0 - 1, iw0 = ox0 - 1;

    ull acc[2][2][4] = {};   // [row s][col c][co pair]
    for (int ci0 = 0; ci0 < 64; ci0 += 8) {
        __syncthreads();
#pragma unroll
        for (int ci = 0; ci < 8; ci++) {
            const float* src = g_c2 + ((size_t)(n * 64 + ci0 + ci) * 56) * 56;
            for (int idx = tid; idx < 18 * 34; idx += 256) {
                int iy = idx / 34, ix = idx - iy * 34;
                int gy = ih0 + iy, gx = iw0 + ix;
                float v = 0.f;
                if (gy >= 0 && gy < 56 && gx >= 0 && gx < 56)
                    v = src[gy * 56 + gx];
                sIn[ci][iy][ix] = v;
            }
        }
        for (int idx = tid; idx < 16 * 72; idx += 256) {
            int c = idx / 72; int rem = idx - c * 72;
            sW[rem][c] = w[((cobg * 16 + c) * 64 + ci0) * 9 + rem];
        }
        __syncthreads();

#pragma unroll
        for (int ci = 0; ci < 8; ci++) {
            // 4x4 input patch: rows sty*2..+3, cols stx*2..+3
            ull pk[4][4];
#pragma unroll
            for (int r = 0; r < 4; r++) {
                float2 a = *(const float2*)&sIn[ci][sty * 2 + r][stx * 2];
                float2 bq = *(const float2*)&sIn[ci][sty * 2 + r][stx * 2 + 2];
                pk[r][0] = pack2(a.x, a.x);
                pk[r][1] = pack2(a.y, a.y);
                pk[r][2] = pack2(bq.x, bq.x);
                pk[r][3] = pack2(bq.y, bq.y);
            }
#pragma unroll
            for (int ky = 0; ky < 3; ky++)
#pragma unroll
                for (int kx = 0; kx < 3; kx++) {
                    const float* wr = &sW[ci * 9 + ky * 3 + kx][wg * 8];
                    const ulonglong2 wp0 = *(const ulonglong2*)(wr + 0);
                    const ulonglong2 wp1 = *(const ulonglong2*)(wr + 4);
#pragma unroll
                    for (int s = 0; s < 2; s++)
#pragma unroll
                        for (int c = 0; c < 2; c++) {
                            ull v = pk[s + ky][c + kx];
                            ffma2(acc[s][c][0], v, wp0.x);
                            ffma2(acc[s][c][1], v, wp0.y);
                            ffma2(acc[s][c][2], v, wp1.x);
                            ffma2(acc[s][c][3], v, wp1.y);
                        }
                }
        }
    }
#pragma unroll
    for (int s = 0; s < 2; s++) {
#pragma unroll
        for (int c = 0; c < 2; c++) {
            const int oy = oy0 + sty * 2 + s, ox = ox0 + stx * 2 + c;
            if (oy < 56 && ox < 56) {
                float a[8];
#pragma unroll
                for (int cp = 0; cp < 4; cp++)
                    unpack2(acc[s][c][cp], a[cp * 2], a[cp * 2 + 1]);
#pragma unroll
                for (int k = 0; k < 8; k++) {
                    int co = cobg * 16 + wg * 8 + k;
                    float v = a[k] + b[co];
                    v = v > 0.f ? v : LEAK * v;
                    g_c3[((n * 128 + co) * 56 + oy) * 56 + ox] = v;
                }
            }
        }
    }
}

// ---------------------------------------------------------------------------
// roi_setup: one thread per (b, roi, point) -> 4 gather indices + 4 weights.
// ---------------------------------------------------------------------------
__global__ void roi_setup_kernel(const float* __restrict__ ROI) {
    int t = blockIdx.x * 256 + threadIdx.x;
    if (t >= 32 * 32 * 100) return;
    int br = t / 100;           // b*32 + roi
    int p  = t - br * 100;      // i*10 + j
    const float* roi = ROI + br * 7;
    float cx = roi[0], cy = roi[1];
    float W1 = roi[2], W2 = roi[3], H1 = roi[4], H2 = roi[5];
    float psi = roi[6];
    float WHx = W1 + W2, WHy = H1 + H2;
    float ofx = (W1 - W2) * 0.5f, ofy = (H1 - H2) * 0.5f;
    float sn = sinf(psi), cs = cosf(psi);
    int i = p / 10, j = p - i * 10;
    float offj = ((float)j - 4.5f) / 10.0f;
    float offi = ((float)i - 4.5f) / 10.0f;
    float gx = offj * WHx - ofx;
    float gy = offi * WHy - ofy;
    float X = gx * cs + gy * sn + cx;   // ggi @ rotM, col 0
    float Y = -gx * sn + gy * cs + cy;  // col 1
    int x0 = (int)floorf(X), x1 = x0 + 1;
    int y0 = (int)floorf(Y), y1 = y0 + 1;
    x0 = min(max(x0, 0), 55); x1 = min(max(x1, 0), 55);
    y0 = min(max(y0, 0), 55); y1 = min(max(y1, 0), 55);
    float x0f = (float)x0, x1f = (float)x1;
    float y0f = (float)y0, y1f = (float)y1;
    float step = (x1f - x0f) * (y1f - y0f);
    step = fminf(fmaxf(step, 0.001f), 2.0f);
    float inv = 1.0f / step;
    float4 wt;
    wt.x = (x1f - X) * (y1f - Y) * inv;   // Ia = img[y0, x0]
    wt.y = (x1f - X) * (Y - y0f) * inv;   // Ib = img[y1, x0]
    wt.z = (X - x0f) * (y1f - Y) * inv;   // Ic = img[y0, x1]
    wt.w = (X - x0f) * (Y - y0f) * inv;   // Id = img[y1, x1]
    int4 ii;
    ii.x = y0 * 56 + x0;
    ii.y = y1 * 56 + x0;
    ii.z = y0 * 56 + x1;
    ii.w = y1 * 56 + x1;
    g_tabI[t] = ii;
    g_tabW[t] = wt;
}

// ---------------------------------------------------------------------------
// roi_gather: reference's raw reshape (C, R*100) -> (R, C, 100):
//   flat[b][r2][c2*100 + p] = bilinear(feat[b], ch=r2*4 + c2/32, roi=c2%32, p)
// ---------------------------------------------------------------------------
__global__ void roi_gather_kernel() {
    const int br2 = blockIdx.x;
    const int b = br2 >> 5, r2 = br2 & 31;
    const int tid = threadIdx.x;
    const float* featb = g_c3 + (size_t)b * 128 * 3136;
    float* outp = g_flat + (size_t)br2 * 12800;
    for (int idx = tid; idx < 12800; idx += 256) {
        int c2 = idx / 100; int p = idx - c2 * 100;
        int roi = c2 & 31;            // ROI actually sampled
        int ch  = r2 * 4 + (c2 >> 5); // channel actually sampled
        int te = (b * 32 + roi) * 100 + p;
        int4   I = g_tabI[te];
        float4 W = g_tabW[te];
        const float* f = featb + ch * 3136;
        outp[idx] = f[I.x] * W.x + f[I.y] * W.y + f[I.z] * W.z + f[I.w] * W.w;
    }
}

// ---------------------------------------------------------------------------
// FC split-K: part[kz] (1024,256) = g_flat[:, kz*6400:(kz+1)*6400] @ fc_w^T
// 64x64 tile, BK=16, 256 threads, 4m x 4n micro-tile. grid (4 n, 16 m, 2 kz)
// ---------------------------------------------------------------------------
__global__ void fc_kernel(const float* __restrict__ Bw) {
    __shared__ __align__(16) float As[16][68];
    __shared__ __align__(16) float Bs[16][68];
    const int tid = threadIdx.x;
    const int m0 = blockIdx.y * 64, n0 = blockIdx.x * 64;
    const int k0base = blockIdx.z * 6400;
    const int lm = tid >> 2, lk = (tid & 3) * 4;
    const int ty = tid >> 4, tx = tid & 15;

    const float* Aptr = g_flat + (size_t)(m0 + lm) * 12800 + k0base + lk;
    const float* Bptr = Bw + (size_t)(n0 + lm) * 12800 + k0base + lk;

    ull acc[4][2] = {};
    for (int k0 = 0; k0 < 6400; k0 += 16) {
        float4 av = *(const float4*)(Aptr + k0);
        float4 bv = *(const float4*)(Bptr + k0);
        As[lk + 0][lm] = av.x; As[lk + 1][lm] = av.y;
        As[lk + 2][lm] = av.z; As[lk + 3][lm] = av.w;
        Bs[lk + 0][lm] = bv.x; Bs[lk + 1][lm] = bv.y;
        Bs[lk + 2][lm] = bv.z; Bs[lk + 3][lm] = bv.w;
        __syncthreads();
#pragma unroll
        for (int kk = 0; kk < 16; kk++) {
            const float4 af = *(const float4*)&As[kk][ty * 4];
            const ulonglong2 bp = *(const ulonglong2*)&Bs[kk][tx * 4];
            ull a0 = pack2(af.x, af.x);
            ull a1 = pack2(af.y, af.y);
            ull a2 = pack2(af.z, af.z);
            ull a3 = pack2(af.w, af.w);
            ffma2(acc[0][0], a0, bp.x); ffma2(acc[0][1], a0, bp.y);
            ffma2(acc[1][0], a1, bp.x); ffma2(acc[1][1], a1, bp.y);
            ffma2(acc[2][0], a2, bp.x); ffma2(acc[2][1], a2, bp.y);
            ffma2(acc[3][0], a3, bp.x); ffma2(acc[3][1], a3, bp.y);
        }
        __syncthreads();
    }
    float* part = g_part + (size_t)blockIdx.z * 1024 * 256;
#pragma unroll
    for (int i = 0; i < 4; i++) {
        int m = m0 + ty * 4 + i;
        float r[4];
        unpack2(acc[i][0], r[0], r[1]);
        unpack2(acc[i][1], r[2], r[3]);
#pragma unroll
        for (int j = 0; j < 4; j++) {
            int nn = n0 + tx * 4 + j;
            part[m * 256 + nn] = r[j];
        }
    }
}

// out = part0 + part1 + bias  (deterministic fixed-order reduce)
__global__ void fc_reduce_kernel(const float* __restrict__ bias,
                                 float* __restrict__ out) {
    int idx = blockIdx.x * 256 + threadIdx.x;   // 1024*256 total
    int nn = idx & 255;
    out[idx] = g_part[idx] + g_part[idx + 1024 * 256] + bias[nn];
}

// ---------------------------------------------------------------------------
extern "C" void kernel_launch(void* const* d_in, const int* in_sizes, int n_in,
                              void* d_out, int out_size) {
    const float* x   = (const float*)d_in[0];
    const float* ROI = (const float*)d_in[1];
    const float* w1  = (const float*)d_in[2];
    const float* b1  = (const float*)d_in[3];
    const float* w2  = (const float*)d_in[4];
    const float* b2  = (const float*)d_in[5];
    const float* w3  = (const float*)d_in[6];
    const float* b3  = (const float*)d_in[7];
    const float* fcw = (const float*)d_in[8];
    const float* fcb = (const float*)d_in[9];
    float* out = (float*)d_out;

    warm_kernel<<<1, 128>>>();   // shifts ncu capture (launch idx 3) onto conv3
    conv1_kernel<<<dim3(7, 7, 32 * 8),  dim3(16, 16)>>>(x, w1, b1);
    conv2_kernel<<<dim3(4, 4, 32 * 2),  dim3(16, 16)>>>(w2, b2);
    conv3_kernel<<<dim3(2, 4, 32 * 8),  dim3(16, 16)>>>(w3, b3);
    roi_setup_kernel<<<(32 * 32 * 100 + 255) / 256, 256>>>(ROI);
    roi_gather_kernel<<<1024, 256>>>();
    fc_kernel<<<dim3(4, 16, 2), 256>>>(fcw);
    fc_reduce_kernel<<<1024, 256>>>(fcb, out);
}

// round 17
// speedup vs baseline: 1.1607x; 1.0253x over previous
#include <cuda_runtime.h>

#define LEAK 0.2f

// Scratch (allocation-free rule: __device__ globals)
__device__ float g_c1[32u*32u*112u*112u];   // 51.4 MB
__device__ float g_c2[32u*64u*56u*56u];     // 25.7 MB
__device__ float g_c3[32u*128u*56u*56u];    // 51.4 MB
__device__ float g_flat[32u*32u*12800u];    // 52.4 MB
__device__ float g_part[4u*1024u*256u];     // FC split-K partials (4 MB)
__device__ int4   g_tabI[32*32*100];        // bilinear gather indices
__device__ float4 g_tabW[32*32*100];        // bilinear weights

typedef unsigned long long ull;

// ---- packed f32x2 helpers (sm_103a; ptxas never emits FFMA2 from C++) ----
__device__ __forceinline__ ull pack2(float x, float y) {
    ull r; asm("mov.b64 %0,{%1,%2};" : "=l"(r) : "f"(x), "f"(y)); return r;
}
__device__ __forceinline__ void unpack2(ull v, float& x, float& y) {
    asm("mov.b64 {%0,%1},%2;" : "=f"(x), "=f"(y) : "l"(v));
}
__device__ __forceinline__ void ffma2(ull& d, ull a, ull b) {
    asm("fma.rn.f32x2 %0,%1,%2,%0;" : "+l"(d) : "l"(a), "l"(b));
}

// no-op: shifts ncu's captured-launch index onto conv3
__global__ void warm_kernel() {}

// ---------------------------------------------------------------------------
// conv1: x(32,3,224,224) -> g_c1(32,32,112,112), k5 s2 p2, leaky
// block (16,16): 16x16 spatial, 4 co per thread (2 f32x2 accs). grid (7,7,256)
// ---------------------------------------------------------------------------
__global__ void conv1_kernel(const float* __restrict__ x,
                             const float* __restrict__ w,
                             const float* __restrict__ b) {
    __shared__ float sIn[3][35][36];
    __shared__ __align__(16) float sW[75][4];   // [ci*25+k][co]
    const int tid = threadIdx.y * 16 + threadIdx.x;
    const int n   = blockIdx.z >> 3;
    const int cob = blockIdx.z & 7;
    const int oy0 = blockIdx.y * 16, ox0 = blockIdx.x * 16;
    const int ih0 = oy0 * 2 - 2, iw0 = ox0 * 2 - 2;

    for (int idx = tid; idx < 3 * 35 * 35; idx += 256) {
        int ci = idx / 1225; int rem = idx - ci * 1225;
        int iy = rem / 35, ix = rem - iy * 35;
        int gy = ih0 + iy, gx = iw0 + ix;
        float v = 0.f;
        if (gy >= 0 && gy < 224 && gx >= 0 && gx < 224)
            v = x[((n * 3 + ci) * 224 + gy) * 224 + gx];
        sIn[ci][iy][ix] = v;
    }
    for (int idx = tid; idx < 300; idx += 256) {
        int c = idx / 75; int rem = idx - c * 75;
        sW[rem][c] = w[(cob * 4 + c) * 75 + rem];
    }
    __syncthreads();

    ull acc01 = 0, acc23 = 0;
    const int ty = threadIdx.y, tx = threadIdx.x;
#pragma unroll
    for (int ci = 0; ci < 3; ci++)
#pragma unroll
        for (int ky = 0; ky < 5; ky++)
#pragma unroll
            for (int kx = 0; kx < 5; kx++) {
                float v = sIn[ci][ty * 2 + ky][tx * 2 + kx];
                ull vv = pack2(v, v);
                const ulonglong2 wv = *(const ulonglong2*)&sW[ci * 25 + ky * 5 + kx][0];
                ffma2(acc01, vv, wv.x);
                ffma2(acc23, vv, wv.y);
            }

    float a[4];
    unpack2(acc01, a[0], a[1]);
    unpack2(acc23, a[2], a[3]);
    const int oy = oy0 + ty, ox = ox0 + tx;   // 112 = 7*16, always in range
#pragma unroll
    for (int c = 0; c < 4; c++) {
        int co = cob * 4 + c;
        float v = a[c] + b[co];
        v = v > 0.f ? v : LEAK * v;
        g_c1[((n * 32 + co) * 112 + oy) * 112 + ox] = v;
    }
}

// ---------------------------------------------------------------------------
// conv2: g_c1(32,32,112,112) -> g_c2(32,64,56,56), k5 s2 p2, leaky
// block (16,32)=512 thr, 4 warpgroups x 16 co = ALL 64 co on ONE staged tile.
// Each 128-thr wg: 2 rows (sty, sty+8) x 16 co. ci chunks of 4.
// grid (4,4,32). smem: 20160 + 25600 = 45.7 KB.
// ---------------------------------------------------------------------------
__global__ void conv2_kernel(const float* __restrict__ w,
                             const float* __restrict__ b) {
    __shared__ float sIn[4][35][36];                  // 20160 B (shared by all wgs)
    __shared__ __align__(16) float sW[100][64];       // [ci*25+k][co], 25600 B
    const int tid = threadIdx.y * 16 + threadIdx.x;
    const int wg  = tid >> 7;                         // 0..3: co quarter
    const int wtid = tid & 127;
    const int sty = wtid >> 4, stx = wtid & 15;
    const int n   = blockIdx.z;
    const int oy0 = blockIdx.y * 16, ox0 = blockIdx.x * 16;
    const int ih0 = oy0 * 2 - 2, iw0 = ox0 * 2 - 2;

    ull acc[2][8] = {};   // [spatial row][co pair]
    for (int ci0 = 0; ci0 < 32; ci0 += 4) {
        __syncthreads();
        for (int idx = tid; idx < 4 * 35 * 35; idx += 512) {
            int ci = idx / 1225; int rem = idx - ci * 1225;
            int iy = rem / 35, ix = rem - iy * 35;
            int gy = ih0 + iy, gx = iw0 + ix;
            float v = 0.f;
            if (gy >= 0 && gy < 112 && gx >= 0 && gx < 112)
                v = g_c1[((n * 32 + ci0 + ci) * 112 + gy) * 112 + gx];
            sIn[ci][iy][ix] = v;
        }
        for (int idx = tid; idx < 64 * 100; idx += 512) {
            int c = idx / 100; int rem = idx - c * 100;
            sW[rem][c] = w[(c * 32 + ci0) * 25 + rem];
        }
        __syncthreads();

#pragma unroll
        for (int ci = 0; ci < 4; ci++) {
#pragma unroll
            for (int ky = 0; ky < 5; ky++)
#pragma unroll
                for (int kx = 0; kx < 5; kx++) {
                    float v0 = sIn[ci][sty * 2 + ky][stx * 2 + kx];
                    float v1 = sIn[ci][sty * 2 + 16 + ky][stx * 2 + kx];
                    ull v0d = pack2(v0, v0);
                    ull v1d = pack2(v1, v1);
                    const float* wr = &sW[ci * 25 + ky * 5 + kx][wg * 16];
                    const ulonglong2 wp0 = *(const ulonglong2*)(wr + 0);
                    const ulonglong2 wp1 = *(const ulonglong2*)(wr + 4);
                    const ulonglong2 wp2 = *(const ulonglong2*)(wr + 8);
                    const ulonglong2 wp3 = *(const ulonglong2*)(wr + 12);
                    ffma2(acc[0][0], v0d, wp0.x); ffma2(acc[0][1], v0d, wp0.y);
                    ffma2(acc[0][2], v0d, wp1.x); ffma2(acc[0][3], v0d, wp1.y);
                    ffma2(acc[0][4], v0d, wp2.x); ffma2(acc[0][5], v0d, wp2.y);
                    ffma2(acc[0][6], v0d, wp3.x); ffma2(acc[0][7], v0d, wp3.y);
                    ffma2(acc[1][0], v1d, wp0.x); ffma2(acc[1][1], v1d, wp0.y);
                    ffma2(acc[1][2], v1d, wp1.x); ffma2(acc[1][3], v1d, wp1.y);
                    ffma2(acc[1][4], v1d, wp2.x); ffma2(acc[1][5], v1d, wp2.y);
                    ffma2(acc[1][6], v1d, wp3.x); ffma2(acc[1][7], v1d, wp3.y);
                }
        }
    }
#pragma unroll
    for (int s = 0; s < 2; s++) {
        const int oy = oy0 + sty + s * 8, ox = ox0 + stx;
        if (oy < 56 && ox < 56) {
            float a[16];
#pragma unroll
            for (int cp = 0; cp < 8; cp++)
                unpack2(acc[s][cp], a[cp * 2], a[cp * 2 + 1]);
#pragma unroll
            for (int c = 0; c < 16; c++) {
                int co = wg * 16 + c;
                float v = a[c] + b[co];
                v = v > 0.f ? v : LEAK * v;
                g_c2[((n * 64 + co) * 56 + oy) * 56 + ox] = v;
            }
        }
    }
}

// ---------------------------------------------------------------------------
// conv3: g_c2(32,64,56,56) -> g_c3(32,128,56,56), k3 s1 p1, leaky
// block (16,32)=512 thr, 4 warpgroups x 8 co (32 co) on ONE staged tile.
// Each 128-thr wg: 2x2 output patch x 8 co. tile 16 rows x 32 cols.
// ci chunks of 8. grid (2,4,32*4). smem: 20736 + 9216 = 30 KB.
// ---------------------------------------------------------------------------
__global__ void conv3_kernel(const float* __restrict__ w,
                             const float* __restrict__ b) {
    __shared__ float sIn[8][18][36];                  // 20736 B (shared)
    __shared__ __align__(16) float sW[72][32];        // [ci*9+k][co], 9216 B
    const int tid = threadIdx.y * 16 + threadIdx.x;
    const int wg  = tid >> 7;                         // 0..3: co quarter
    const int wtid = tid & 127;
    const int sty = wtid >> 4, stx = wtid & 15;
    const int n    = blockIdx.z >> 2;
    const int cobg = blockIdx.z & 3;                  // 4 groups of 32 co
    const int oy0 = blockIdx.y * 16, ox0 = blockIdx.x * 32;
    const int ih0 = oy0 - 1, iw0 = ox0 - 1;

    ull acc[2][2][4] = {};   // [row s][col c][co pair]
    for (int ci0 = 0; ci0 < 64; ci0 += 8) {
        __syncthreads();
#pragma unroll
        for (int ci = 0; ci < 8; ci++) {
            const float* src = g_c2 + ((size_t)(n * 64 + ci0 + ci) * 56) * 56;
            for (int idx = tid; idx < 18 * 34; idx += 512) {
                int iy = idx / 34, ix = idx - iy * 34;
                int gy = ih0 + iy, gx = iw0 + ix;
                float v = 0.f;
                if (gy >= 0 && gy < 56 && gx >= 0 && gx < 56)
                    v = src[gy * 56 + gx];
                sIn[ci][iy][ix] = v;
            }
        }
        for (int idx = tid; idx < 32 * 72; idx += 512) {
            int c = idx / 72; int rem = idx - c * 72;
            sW[rem][c] = w[((cobg * 32 + c) * 64 + ci0) * 9 + rem];
        }
        __syncthreads();

#pragma unroll
        for (int ci = 0; ci < 8; ci++) {
            // 4x4 input patch: rows sty*2..+3, cols stx*2..+3
            ull pk[4][4];
#pragma unroll
            for (int r = 0; r < 4; r++) {
                float2 a = *(const float2*)&sIn[ci][sty * 2 + r][stx * 2];
                float2 bq = *(const float2*)&sIn[ci][sty * 2 + r][stx * 2 + 2];
                pk[r][0] = pack2(a.x, a.x);
                pk[r][1] = pack2(a.y, a.y);
                pk[r][2] = pack2(bq.x, bq.x);
                pk[r][3] = pack2(bq.y, bq.y);
            }
#pragma unroll
            for (int ky = 0; ky < 3; ky++)
#pragma unroll
                for (int kx = 0; kx < 3; kx++) {
                    const float* wr = &sW[ci * 9 + ky * 3 + kx][wg * 8];
                    const ulonglong2 wp0 = *(const ulonglong2*)(wr + 0);
                    const ulonglong2 wp1 = *(const ulonglong2*)(wr + 4);
#pragma unroll
                    for (int s = 0; s < 2; s++)
#pragma unroll
                        for (int c = 0; c < 2; c++) {
                            ull v = pk[s + ky][c + kx];
                            ffma2(acc[s][c][0], v, wp0.x);
                            ffma2(acc[s][c][1], v, wp0.y);
                            ffma2(acc[s][c][2], v, wp1.x);
                            ffma2(acc[s][c][3], v, wp1.y);
                        }
                }
        }
    }
#pragma unroll
    for (int s = 0; s < 2; s++) {
#pragma unroll
        for (int c = 0; c < 2; c++) {
            const int oy = oy0 + sty * 2 + s, ox = ox0 + stx * 2 + c;
            if (oy < 56 && ox < 56) {
                float a[8];
#pragma unroll
                for (int cp = 0; cp < 4; cp++)
                    unpack2(acc[s][c][cp], a[cp * 2], a[cp * 2 + 1]);
#pragma unroll
                for (int k = 0; k < 8; k++) {
                    int co = cobg * 32 + wg * 8 + k;
                    float v = a[k] + b[co];
                    v = v > 0.f ? v : LEAK * v;
                    g_c3[((n * 128 + co) * 56 + oy) * 56 + ox] = v;
                }
            }
        }
    }
}

// ---------------------------------------------------------------------------
// roi_setup: one thread per (b, roi, point) -> 4 gather indices + 4 weights.
// ---------------------------------------------------------------------------
__global__ void roi_setup_kernel(const float* __restrict__ ROI) {
    int t = blockIdx.x * 256 + threadIdx.x;
    if (t >= 32 * 32 * 100) return;
    int br = t / 100;           // b*32 + roi
    int p  = t - br * 100;      // i*10 + j
    const float* roi = ROI + br * 7;
    float cx = roi[0], cy = roi[1];
    float W1 = roi[2], W2 = roi[3], H1 = roi[4], H2 = roi[5];
    float psi = roi[6];
    float WHx = W1 + W2, WHy = H1 + H2;
    float ofx = (W1 - W2) * 0.5f, ofy = (H1 - H2) * 0.5f;
    float sn = sinf(psi), cs = cosf(psi);
    int i = p / 10, j = p - i * 10;
    float offj = ((float)j - 4.5f) / 10.0f;
    float offi = ((float)i - 4.5f) / 10.0f;
    float gx = offj * WHx - ofx;
    float gy = offi * WHy - ofy;
    float X = gx * cs + gy * sn + cx;   // ggi @ rotM, col 0
    float Y = -gx * sn + gy * cs + cy;  // col 1
    int x0 = (int)floorf(X), x1 = x0 + 1;
    int y0 = (int)floorf(Y), y1 = y0 + 1;
    x0 = min(max(x0, 0), 55); x1 = min(max(x1, 0), 55);
    y0 = min(max(y0, 0), 55); y1 = min(max(y1, 0), 55);
    float x0f = (float)x0, x1f = (float)x1;
    float y0f = (float)y0, y1f = (float)y1;
    float step = (x1f - x0f) * (y1f - y0f);
    step = fminf(fmaxf(step, 0.001f), 2.0f);
    float inv = 1.0f / step;
    float4 wt;
    wt.x = (x1f - X) * (y1f - Y) * inv;   // Ia = img[y0, x0]
    wt.y = (x1f - X) * (Y - y0f) * inv;   // Ib = img[y1, x0]
    wt.z = (X - x0f) * (y1f - Y) * inv;   // Ic = img[y0, x1]
    wt.w = (X - x0f) * (Y - y0f) * inv;   // Id = img[y1, x1]
    int4 ii;
    ii.x = y0 * 56 + x0;
    ii.y = y1 * 56 + x0;
    ii.z = y0 * 56 + x1;
    ii.w = y1 * 56 + x1;
    g_tabI[t] = ii;
    g_tabW[t] = wt;
}

// ---------------------------------------------------------------------------
// roi_gather: reference's raw reshape (C, R*100) -> (R, C, 100):
//   flat[b][r2][c2*100 + p] = bilinear(feat[b], ch=r2*4 + c2/32, roi=c2%32, p)
// ---------------------------------------------------------------------------
__global__ void roi_gather_kernel() {
    const int br2 = blockIdx.x;
    const int b = br2 >> 5, r2 = br2 & 31;
    const int tid = threadIdx.x;
    const float* featb = g_c3 + (size_t)b * 128 * 3136;
    float* outp = g_flat + (size_t)br2 * 12800;
    for (int idx = tid; idx < 12800; idx += 256) {
        int c2 = idx / 100; int p = idx - c2 * 100;
        int roi = c2 & 31;            // ROI actually sampled
        int ch  = r2 * 4 + (c2 >> 5); // channel actually sampled
        int te = (b * 32 + roi) * 100 + p;
        int4   I = g_tabI[te];
        float4 W = g_tabW[te];
        const float* f = featb + ch * 3136;
        outp[idx] = f[I.x] * W.x + f[I.y] * W.y + f[I.z] * W.z + f[I.w] * W.w;
    }
}

// ---------------------------------------------------------------------------
// FC split-K: part[kz] (1024,256) = g_flat[:, kz*3200:(kz+1)*3200] @ fc_w^T
// 64x64 tile, BK=16, 256 threads, 4m x 4n micro-tile. grid (4 n, 16 m, 4 kz)
// ---------------------------------------------------------------------------
__global__ void fc_kernel(const float* __restrict__ Bw) {
    __shared__ __align__(16) float As[16][68];
    __shared__ __align__(16) float Bs[16][68];
    const int tid = threadIdx.x;
    const int m0 = blockIdx.y * 64, n0 = blockIdx.x * 64;
    const int k0base = blockIdx.z * 3200;
    const int lm = tid >> 2, lk = (tid & 3) * 4;
    const int ty = tid >> 4, tx = tid & 15;

    const float* Aptr = g_flat + (size_t)(m0 + lm) * 12800 + k0base + lk;
    const float* Bptr = Bw + (size_t)(n0 + lm) * 12800 + k0base + lk;

    ull acc[4][2] = {};
    for (int k0 = 0; k0 < 3200; k0 += 16) {
        float4 av = *(const float4*)(Aptr + k0);
        float4 bv = *(const float4*)(Bptr + k0);
        As[lk + 0][lm] = av.x; As[lk + 1][lm] = av.y;
        As[lk + 2][lm] = av.z; As[lk + 3][lm] = av.w;
        Bs[lk + 0][lm] = bv.x; Bs[lk + 1][lm] = bv.y;
        Bs[lk + 2][lm] = bv.z; Bs[lk + 3][lm] = bv.w;
        __syncthreads();
#pragma unroll
        for (int kk = 0; kk < 16; kk++) {
            const float4 af = *(const float4*)&As[kk][ty * 4];
            const ulonglong2 bp = *(const ulonglong2*)&Bs[kk][tx * 4];
            ull a0 = pack2(af.x, af.x);
            ull a1 = pack2(af.y, af.y);
            ull a2 = pack2(af.z, af.z);
            ull a3 = pack2(af.w, af.w);
            ffma2(acc[0][0], a0, bp.x); ffma2(acc[0][1], a0, bp.y);
            ffma2(acc[1][0], a1, bp.x); ffma2(acc[1][1], a1, bp.y);
            ffma2(acc[2][0], a2, bp.x); ffma2(acc[2][1], a2, bp.y);
            ffma2(acc[3][0], a3, bp.x); ffma2(acc[3][1], a3, bp.y);
        }
        __syncthreads();
    }
    float* part = g_part + (size_t)blockIdx.z * 1024 * 256;
#pragma unroll
    for (int i = 0; i < 4; i++) {
        int m = m0 + ty * 4 + i;
        float r[4];
        unpack2(acc[i][0], r[0], r[1]);
        unpack2(acc[i][1], r[2], r[3]);
#pragma unroll
        for (int j = 0; j < 4; j++) {
            int nn = n0 + tx * 4 + j;
            part[m * 256 + nn] = r[j];
        }
    }
}

// out = p0+p1+p2+p3 + bias  (deterministic fixed-order reduce)
__global__ void fc_reduce_kernel(const float* __restrict__ bias,
                                 float* __restrict__ out) {
    int idx = blockIdx.x * 256 + threadIdx.x;   // 1024*256 total
    int nn = idx & 255;
    const int P = 1024 * 256;
    out[idx] = ((g_part[idx] + g_part[idx + P]) +
                (g_part[idx + 2 * P] + g_part[idx + 3 * P])) + bias[nn];
}

// ---------------------------------------------------------------------------
extern "C" void kernel_launch(void* const* d_in, const int* in_sizes, int n_in,
                              void* d_out, int out_size) {
    const float* x   = (const float*)d_in[0];
    const float* ROI = (const float*)d_in[1];
    const float* w1  = (const float*)d_in[2];
    const float* b1  = (const float*)d_in[3];
    const float* w2  = (const float*)d_in[4];
    const float* b2  = (const float*)d_in[5];
    const float* w3  = (const float*)d_in[6];
    const float* b3  = (const float*)d_in[7];
    const float* fcw = (const float*)d_in[8];
    const float* fcb = (const float*)d_in[9];
    float* out = (float*)d_out;

    warm_kernel<<<1, 128>>>();   // shifts ncu capture (launch idx 3) onto conv3
    conv1_kernel<<<dim3(7, 7, 32 * 8),  dim3(16, 16)>>>(x, w1, b1);
    conv2_kernel<<<dim3(4, 4, 32),      dim3(16, 32)>>>(w2, b2);
    conv3_kernel<<<dim3(2, 4, 32 * 4),  dim3(16, 32)>>>(w3, b3);
    roi_setup_kernel<<<(32 * 32 * 100 + 255) / 256, 256>>>(ROI);
    roi_gather_kernel<<<1024, 256>>>();
    fc_kernel<<<dim3(4, 16, 4), 256>>>(fcw);
    fc_reduce_kernel<<<1024, 256>>>(fcb, out);
}